// round 2
// baseline (speedup 1.0000x reference)
#include <cuda_runtime.h>
#include <math.h>

#define B 16
#define I_IN 256
#define H 512
#define O_OUT 256
#define A 1024
#define M 64
#define R 4
#define IFW 471
#define N4H 2048
#define NCOLS3 (IFW + O_OUT)   // 727
#define NB 148                 // persistent grid
#define NT 512

// interface offsets
#define OFF_KR     0
#define OFF_BETAR  256
#define OFF_KW     260
#define OFF_BETAW  324
#define OFF_ERASE  325
#define OFF_WRITEV 389
#define OFF_FREE   453
#define OFF_GA     457
#define OFF_GW     458
#define OFF_PI     459

// ----------------- device scratch -----------------
__device__ float  g_zpart[8][B][N4H];
__device__ float  g_h[B][H];
__device__ float  g_iface[B][IFW];
__device__ float  g_outhid[B][O_OUT];
__device__ float  g_ww[B][A];
__device__ float  g_S[B][R];
__device__ float  g_T[B][R];
__device__ float  g_mem[B][A][M];
__device__ float  g_cr[B][R][A];
__device__ double g_PQ[B][R][A];          // packed (p, q) f32x2
__device__ double g_UVp[16][B][R][A];     // packed (u, v) partials per stripe
__device__ float  g_rvpart[2][B][R * M];

// barrier state (persists across replays; sense-reversing)
__device__ int g_bar_count = 0;
__device__ volatile unsigned g_bar_gen = 0;

__device__ __forceinline__ void gridbar() {
    __syncthreads();
    if (threadIdx.x == 0) {
        __threadfence();
        unsigned my = g_bar_gen;
        if (atomicAdd(&g_bar_count, 1) == NB - 1) {
            g_bar_count = 0;
            __threadfence();
            g_bar_gen = my + 1;
        } else {
            while (g_bar_gen == my) {}
        }
        __threadfence();
    }
    __syncthreads();
}

__device__ __forceinline__ float sigf(float x) { return 1.f / (1.f + __expf(-x)); }
__device__ __forceinline__ float oneplusf(float x) {
    return 1.f + (x > 20.f ? x : log1pf(__expf(x)));
}

// packed f32x2 helpers (double as bit-carrier)
__device__ __forceinline__ double pack2(float lo, float hi) {
    double d; asm("mov.b64 %0, {%1,%2};" : "=d"(d) : "f"(lo), "f"(hi)); return d;
}
__device__ __forceinline__ double splat2(float v) {
    double d; asm("mov.b64 %0, {%1,%1};" : "=d"(d) : "f"(v)); return d;
}
__device__ __forceinline__ void fma2(double& acc, double a, double b) {
    asm("fma.rn.f32x2 %0, %1, %2, %3;" : "=d"(acc) : "d"(a), "d"(b), "d"(acc));
}
__device__ __forceinline__ double add2(double a, double b) {
    double d; asm("add.rn.f32x2 %0, %1, %2;" : "=d"(d) : "d"(a), "d"(b)); return d;
}
__device__ __forceinline__ float2 unpack2(double d) {
    float2 f; asm("mov.b64 {%0,%1}, %2;" : "=f"(f.x), "=f"(f.y) : "d"(d)); return f;
}

// swizzle for the k7 pack table (idx = a*4 + r); keeps LDS conflicts <= 2-way
__device__ __forceinline__ int swz(int idx) { return idx ^ (((idx >> 9) & 7) << 2); }

// ----------------- shared union -----------------
struct SmemP1 { float in[B][128]; };
struct SmemP4 {
    float val[A]; float tmp[A]; int idx[A]; float cw[A];
    float red[16]; float scal[8]; float kw[M];
};
struct SmemK5 { float kr[R][M]; float er[M]; float wv[M]; float beta[R]; float kn[R]; };
struct SmemK7 { double pack[A * 4]; };     // 32 KB
struct SmemP7 { float wr[R][NT]; float pi[R][3]; };
struct SmemP8 { float rv[2][256]; };
union SmemAll {
    SmemP1 p1; SmemP4 p4; SmemK5 k5; SmemK7 k7; SmemP7 p7; SmemP8 p8;
};

template <int W>
__device__ __forceinline__ float blockSum(float v, float* s_red) {
    int lane = threadIdx.x & 31, w = threadIdx.x >> 5;
#pragma unroll
    for (int o = 16; o; o >>= 1) v += __shfl_down_sync(0xffffffffu, v, o);
    if (lane == 0) s_red[w] = v;
    __syncthreads();
    if (w == 0) {
        float x = (lane < W / 32) ? s_red[lane] : 0.f;
#pragma unroll
        for (int o = 16; o; o >>= 1) x += __shfl_down_sync(0xffffffffu, x, o);
        if (lane == 0) s_red[0] = x;
    }
    __syncthreads();
    float res = s_red[0];
    __syncthreads();
    return res;
}
template <int W>
__device__ __forceinline__ float blockMax(float v, float* s_red) {
    int lane = threadIdx.x & 31, w = threadIdx.x >> 5;
#pragma unroll
    for (int o = 16; o; o >>= 1) v = fmaxf(v, __shfl_down_sync(0xffffffffu, v, o));
    if (lane == 0) s_red[w] = v;
    __syncthreads();
    if (w == 0) {
        float x = (lane < W / 32) ? s_red[lane] : -1e30f;
#pragma unroll
        for (int o = 16; o; o >>= 1) x = fmaxf(x, __shfl_down_sync(0xffffffffu, x, o));
        if (lane == 0) s_red[0] = x;
    }
    __syncthreads();
    float res = s_red[0];
    __syncthreads();
    return res;
}

// ======================= fused persistent kernel =======================
__global__ void __launch_bounds__(NT, 1)
dnc_fused(const float* __restrict__ x, const float* __restrict__ h_prev,
          const float* __restrict__ c_prev, const float* __restrict__ mem_prev,
          const float* __restrict__ rw_prev, const float* __restrict__ ww_prev,
          const float* __restrict__ usage_prev, const float* __restrict__ prec_prev,
          const float* __restrict__ link_prev, const float* __restrict__ rv_prev,
          const float* __restrict__ Wx, const float* __restrict__ Wh,
          const float* __restrict__ b_lstm, const float* __restrict__ W_hid,
          const float* __restrict__ b_hid, const float* __restrict__ W_if,
          const float* __restrict__ b_if, const float* __restrict__ W_rd,
          const float* __restrict__ b_rd, float* __restrict__ out) {
    __shared__ SmemAll smem;
    const int tid = threadIdx.x;
    const int bid = blockIdx.x;

    // ---------------- P1: z partial GEMM (32 tasks: 4 n-tiles x 8 k-chunks) ----
    for (int task = bid; task < 32; task += NB) {
        __syncthreads();
        int nbase = (task & 3) * 512;
        int kc = task >> 2;
        int kbase = kc * 128;
        for (int idx = tid; idx < B * 128; idx += NT) {
            int b = idx >> 7, kl = idx & 127;
            int kk = kbase + kl;
            float v;
            if (kk < 256) v = x[b * I_IN + kk];
            else if (kk < 512) v = rv_prev[b * 256 + (kk - 256)];
            else v = h_prev[b * H + (kk - 512)];
            smem.p1.in[b][kl] = v;
        }
        __syncthreads();
        int n = nbase + tid;
        const float* W = (kbase < 512) ? (Wx + (size_t)kbase * N4H)
                                       : (Wh + (size_t)(kbase - 512) * N4H);
        float acc[B];
#pragma unroll
        for (int b = 0; b < B; b++) acc[b] = 0.f;
#pragma unroll 4
        for (int kl = 0; kl < 128; kl++) {
            float w = W[(size_t)kl * N4H + n];
#pragma unroll
            for (int b = 0; b < B; b++) acc[b] = fmaf(w, smem.p1.in[b][kl], acc[b]);
        }
#pragma unroll
        for (int b = 0; b < B; b++) g_zpart[kc][b][n] = acc[b];
    }
    gridbar();

    // ---------------- P2: LSTM elementwise (16 tasks) ----
    for (int task = bid; task < 16; task += NB) {
        int idx = task * NT + tid;
        int b = idx >> 9, hh = idx & 511;
        float zv[4];
#pragma unroll
        for (int g = 0; g < 4; g++) {
            int n = g * H + hh;
            float s = b_lstm[n];
#pragma unroll
            for (int kc = 0; kc < 8; kc++) s += g_zpart[kc][b][n];
            zv[g] = s;
        }
        float c = sigf(zv[1]) * c_prev[idx] + sigf(zv[0]) * tanhf(zv[2]);
        g_h[b][hh] = sigf(zv[3]) * tanhf(c);
    }
    gridbar();

    // ---------------- P3: iface + out_hidden GEMM (23 tasks, full K) ----
    for (int task = bid; task < 23; task += NB) {
        int idx = task * NT + tid;
        if (idx < B * NCOLS3) {
            int col = idx % NCOLS3, b = idx / NCOLS3;
            const float* hrow = g_h[b];
            float acc = 0.f;
            if (col < IFW) {
                const float* W = W_if + col;
#pragma unroll 8
                for (int k = 0; k < H; k++) acc = fmaf(hrow[k], W[(size_t)k * IFW], acc);
                g_iface[b][col] = acc + b_if[col];
            } else {
                int c2 = col - IFW;
                const float* W = W_hid + c2;
#pragma unroll 8
                for (int k = 0; k < H; k++) acc = fmaf(hrow[k], W[(size_t)k * O_OUT], acc);
                g_outhid[b][c2] = acc + b_hid[c2];
            }
        }
    }
    gridbar();

    // ---------------- P4: cwlog + usage + sort + alloc + ww + S,T (16 tasks) ----
    for (int b = bid; b < B; b += NB) {
        __syncthreads();
        if (tid < M) smem.p4.kw[tid] = g_iface[b][OFF_KW + tid];
        if (tid == 0) {
            smem.p4.scal[0] = oneplusf(g_iface[b][OFF_BETAW]);
            smem.p4.scal[1] = sigf(g_iface[b][OFF_GA]);
            smem.p4.scal[2] = sigf(g_iface[b][OFF_GW]);
        }
        if (tid < R) smem.p4.scal[4 + tid] = sigf(g_iface[b][OFF_FREE + tid]);
        __syncthreads();
        float kn2 = 0.f;
#pragma unroll
        for (int m = 0; m < M; m++) { float v = smem.p4.kw[m]; kn2 = fmaf(v, v, kn2); }
        float knorm = sqrtf(kn2);
        float betaw = smem.p4.scal[0];
        // cwlog into s_cw (logits)
        for (int ii = 0; ii < 2; ii++) {
            int a = tid + ii * 512;
            const float4* mrow =
                reinterpret_cast<const float4*>(mem_prev + ((size_t)(b * A + a)) * M);
            float d = 0.f, n = 0.f;
#pragma unroll
            for (int q = 0; q < 16; q++) {
                float4 v = mrow[q];
                int m0 = q * 4;
                d += v.x * smem.p4.kw[m0] + v.y * smem.p4.kw[m0 + 1] +
                     v.z * smem.p4.kw[m0 + 2] + v.w * smem.p4.kw[m0 + 3];
                n += v.x * v.x + v.y * v.y + v.z * v.z + v.w * v.w;
            }
            smem.p4.cw[a] = betaw * d / (knorm * sqrtf(n) + 1e-6f);
        }
        // usage update
        for (int ii = 0; ii < 2; ii++) {
            int a = tid + ii * 512;
            float psi = 1.f;
#pragma unroll
            for (int r = 0; r < R; r++)
                psi *= (1.f - smem.p4.scal[4 + r] * rw_prev[(b * R + r) * A + a]);
            float u = usage_prev[b * A + a], w = ww_prev[b * A + a];
            smem.p4.val[a] = (u + w - u * w) * psi;
            smem.p4.idx[a] = a;
        }
        __syncthreads();
        // bitonic sort ascending (payload = original index)
        for (int k = 2; k <= A; k <<= 1) {
            for (int j = k >> 1; j > 0; j >>= 1) {
                for (int i = tid; i < A; i += NT) {
                    int l = i ^ j;
                    if (l > i) {
                        bool up = ((i & k) == 0);
                        float vi = smem.p4.val[i], vl = smem.p4.val[l];
                        if ((vi > vl) == up) {
                            smem.p4.val[i] = vl; smem.p4.val[l] = vi;
                            int t = smem.p4.idx[i]; smem.p4.idx[i] = smem.p4.idx[l];
                            smem.p4.idx[l] = t;
                        }
                    }
                }
                __syncthreads();
            }
        }
        float su0 = smem.p4.val[tid], su1 = smem.p4.val[tid + 512];
        // inclusive cumprod (Hillis-Steele)
        {
            float* src = smem.p4.val;
            float* dst = smem.p4.tmp;
            for (int off = 1; off < A; off <<= 1) {
                for (int i = tid; i < A; i += NT)
                    dst[i] = (i >= off) ? src[i - off] * src[i] : src[i];
                __syncthreads();
                float* t = src; src = dst; dst = t;
            }
        }
        // alloc (scattered back) into s_tmp
        {
            float cpe0 = (tid == 0) ? 1.f : smem.p4.val[tid - 1];
            float cpe1 = smem.p4.val[tid + 511];
            smem.p4.tmp[smem.p4.idx[tid]] = (1.f - su0) * cpe0;
            smem.p4.tmp[smem.p4.idx[tid + 512]] = (1.f - su1) * cpe1;
        }
        __syncthreads();
        // c_w softmax in place
        float l0 = smem.p4.cw[tid], l1 = smem.p4.cw[tid + 512];
        float mx = blockMax<NT>(fmaxf(l0, l1), smem.p4.red);
        float e0 = __expf(l0 - mx), e1 = __expf(l1 - mx);
        float ssum = blockSum<NT>(e0 + e1, smem.p4.red);
        float inv = 1.f / ssum;
        smem.p4.cw[tid] = e0 * inv;
        smem.p4.cw[tid + 512] = e1 * inv;
        __syncthreads();
        // ww + S,T
        float ga = smem.p4.scal[1], gw = smem.p4.scal[2];
        float sS[R] = {0, 0, 0, 0}, sT[R] = {0, 0, 0, 0};
        for (int ii = 0; ii < 2; ii++) {
            int a = tid + ii * 512;
            float wwv = gw * (ga * smem.p4.tmp[a] + (1.f - ga) * smem.p4.cw[a]);
            g_ww[b][a] = wwv;
            float pp = prec_prev[b * A + a];
#pragma unroll
            for (int r = 0; r < R; r++) {
                float rw = rw_prev[(b * R + r) * A + a];
                sS[r] = fmaf(pp, rw, sS[r]);
                sT[r] = fmaf(wwv, rw, sT[r]);
            }
        }
#pragma unroll
        for (int r = 0; r < R; r++) {
            float v = blockSum<NT>(sS[r], smem.p4.red);
            if (tid == 0) g_S[b][r] = v;
            v = blockSum<NT>(sT[r], smem.p4.red);
            if (tid == 0) g_T[b][r] = v;
        }
    }
    gridbar();

    // ---------------- P5: mem write + c_r logits (64) AND link pass (256) ----
    for (int task = bid; task < 320; task += NB) {
        __syncthreads();
        if (task < 64) {
            // k5: b = task>>2, chunk = task&3 (256 rows)
            int b = task >> 2, chunk = task & 3;
            int warp = tid >> 5, lane = tid & 31;
            if (tid < 256) {
                int r = tid >> 6, m = tid & 63;
                smem.k5.kr[r][m] = g_iface[b][OFF_KR + r * M + m];
            }
            if (tid < M) smem.k5.er[tid] = sigf(g_iface[b][OFF_ERASE + tid]);
            else if (tid < 2 * M) smem.k5.wv[tid - M] = g_iface[b][OFF_WRITEV + (tid - M)];
            __syncthreads();
            if (tid < R) {
                smem.k5.beta[tid] = oneplusf(g_iface[b][OFF_BETAR + tid]);
                float s = 0.f;
#pragma unroll
                for (int m = 0; m < M; m++) {
                    float v = smem.k5.kr[tid][m];
                    s = fmaf(v, v, s);
                }
                smem.k5.kn[tid] = sqrtf(s);
            }
            __syncthreads();
            for (int rr = 0; rr < 16; rr++) {
                int a = chunk * 256 + warp * 16 + rr;
                float w = g_ww[b][a];
                int m0 = lane * 2;
                const float2 v = *reinterpret_cast<const float2*>(
                    mem_prev + ((size_t)(b * A + a)) * M + m0);
                float n0 = v.x * (1.f - w * smem.k5.er[m0]) + w * smem.k5.wv[m0];
                float n1 = v.y * (1.f - w * smem.k5.er[m0 + 1]) + w * smem.k5.wv[m0 + 1];
                *reinterpret_cast<float2*>(&g_mem[b][a][m0]) = make_float2(n0, n1);
                float nn = n0 * n0 + n1 * n1;
                float d[R];
#pragma unroll
                for (int r = 0; r < R; r++)
                    d[r] = n0 * smem.k5.kr[r][m0] + n1 * smem.k5.kr[r][m0 + 1];
#pragma unroll
                for (int o = 16; o; o >>= 1) {
                    nn += __shfl_down_sync(0xffffffffu, nn, o);
#pragma unroll
                    for (int r = 0; r < R; r++)
                        d[r] += __shfl_down_sync(0xffffffffu, d[r], o);
                }
                if (lane == 0) {
                    float mn = sqrtf(nn);
#pragma unroll
                    for (int r = 0; r < R; r++)
                        g_cr[b][r][a] = smem.k5.beta[r] * d[r] / (smem.k5.kn[r] * mn + 1e-6f);
                }
            }
        } else {
            // k7: link pass, t2 = task-64: b = t2>>4, stripe = t2&15 (64 rows)
            int t2 = task - 64;
            int b = t2 >> 4, stripe = t2 & 15;
            // load pack table: pack[a*4+r] = (rw[r][a], ww[a]*rw[r][a])
            for (int a = tid; a < A; a += NT) {
                float w = g_ww[b][a];
#pragma unroll
                for (int r = 0; r < R; r++) {
                    float rw = rw_prev[(b * R + r) * A + a];
                    smem.k7.pack[swz(a * 4 + r)] = pack2(rw, w * rw);
                }
            }
            __syncthreads();
            const float* Lp = link_prev + (size_t)b * A * A;
            int jbase = stripe * 64;
            // Phase A: column partials (u,v) for cols 2t,2t+1 over 64 rows
            double uv0[R], uv1[R];
#pragma unroll
            for (int r = 0; r < R; r++) { uv0[r] = 0.0; uv1[r] = 0.0; }
#pragma unroll 2
            for (int j = 0; j < 64; j++) {
                const float2 val =
                    *reinterpret_cast<const float2*>(Lp + (size_t)(jbase + j) * A + 2 * tid);
                double slo = splat2(val.x), shi = splat2(val.y);
                int j4 = (jbase + j) * 4;
#pragma unroll
                for (int r = 0; r < R; r++) {
                    double pk = smem.k7.pack[swz(j4 + r)];
                    fma2(uv0[r], slo, pk);
                    fma2(uv1[r], shi, pk);
                }
            }
#pragma unroll
            for (int r = 0; r < R; r++) {
                g_UVp[stripe][b][r][2 * tid] = uv0[r];
                g_UVp[stripe][b][r][2 * tid + 1] = uv1[r];
            }
            // Phase B: row dots (p,q) — rows re-read from L2
            int rowl = tid >> 3, seg = tid & 7;
            const float* Lr = Lp + (size_t)(jbase + rowl) * A + seg * 128;
            double pq[R] = {0.0, 0.0, 0.0, 0.0};
#pragma unroll 4
            for (int c = 0; c < 128; c += 4) {
                float4 val = *reinterpret_cast<const float4*>(Lr + c);
                int col4 = (seg * 128 + c) * 4;
                double s0 = splat2(val.x), s1 = splat2(val.y);
                double s2 = splat2(val.z), s3 = splat2(val.w);
#pragma unroll
                for (int r = 0; r < R; r++) {
                    fma2(pq[r], s0, smem.k7.pack[swz(col4 + r)]);
                    fma2(pq[r], s1, smem.k7.pack[swz(col4 + 4 + r)]);
                    fma2(pq[r], s2, smem.k7.pack[swz(col4 + 8 + r)]);
                    fma2(pq[r], s3, smem.k7.pack[swz(col4 + 12 + r)]);
                }
            }
#pragma unroll
            for (int r = 0; r < R; r++) {
                pq[r] = add2(pq[r], __shfl_xor_sync(0xffffffffu, pq[r], 1));
                pq[r] = add2(pq[r], __shfl_xor_sync(0xffffffffu, pq[r], 2));
                pq[r] = add2(pq[r], __shfl_xor_sync(0xffffffffu, pq[r], 4));
            }
            if (seg == 0) {
                int row = jbase + rowl;
#pragma unroll
                for (int r = 0; r < R; r++) g_PQ[b][r][row] = pq[r];
            }
        }
    }
    gridbar();

    // ---------------- P6: softmax of c_r over A (64 tasks) ----
    for (int task = bid; task < B * R; task += NB) {
        __syncthreads();
        int b = task >> 2, r = task & 3;
        float* row = g_cr[b][r];
        float l0 = row[tid], l1 = row[tid + 512];
        float mx = blockMax<NT>(fmaxf(l0, l1), smem.p4.red);
        float e0 = __expf(l0 - mx), e1 = __expf(l1 - mx);
        float s = blockSum<NT>(e0 + e1, smem.p4.red);
        float inv = 1.f / s;
        row[tid] = e0 * inv;
        row[tid + 512] = e1 * inv;
    }
    gridbar();

    // ---------------- P7: read weights + partial read vectors (32 tasks) ----
    for (int task = bid; task < 32; task += NB) {
        __syncthreads();
        int b = task >> 1, chunk = task & 1;
        if (tid < R) {
            float l0 = g_iface[b][OFF_PI + tid * 3 + 0];
            float l1 = g_iface[b][OFF_PI + tid * 3 + 1];
            float l2 = g_iface[b][OFF_PI + tid * 3 + 2];
            float mx = fmaxf(l0, fmaxf(l1, l2));
            float e0 = __expf(l0 - mx), e1 = __expf(l1 - mx), e2 = __expf(l2 - mx);
            float inv = 1.f / (e0 + e1 + e2);
            smem.p7.pi[tid][0] = e0 * inv;
            smem.p7.pi[tid][1] = e1 * inv;
            smem.p7.pi[tid][2] = e2 * inv;
        }
        __syncthreads();
        int a = chunk * 512 + tid;
        float ww = g_ww[b][a];
        float pp = prec_prev[b * A + a];
#pragma unroll
        for (int r = 0; r < R; r++) {
            float rw = rw_prev[(b * R + r) * A + a];
            float2 PQ = unpack2(g_PQ[b][r][a]);
            double uvs = g_UVp[0][b][r][a];
#pragma unroll
            for (int s16 = 1; s16 < 16; s16++) uvs = add2(uvs, g_UVp[s16][b][r][a]);
            float2 UV = unpack2(uvs);
            float Sr = g_S[b][r], Tr = g_T[b][r];
            float fwd = (1.f - ww) * PQ.x - PQ.y + ww * (Sr - pp * rw);
            float bwd = (1.f - ww) * UV.x - UV.y + pp * (Tr - ww * rw);
            float cr = g_cr[b][r][a];
            smem.p7.wr[r][tid] =
                smem.p7.pi[r][0] * bwd + smem.p7.pi[r][1] * cr + smem.p7.pi[r][2] * fwd;
        }
        __syncthreads();
        int o = tid >> 1, half = tid & 1;
        int r = o >> 6, m = o & 63;
        float acc = 0.f;
        const float* memb = &g_mem[b][chunk * 512][0];
#pragma unroll 4
        for (int i = 0; i < 256; i++) {
            int slot = half * 256 + i;
            acc = fmaf(smem.p7.wr[r][slot], memb[(size_t)slot * M + m], acc);
        }
        acc += __shfl_xor_sync(0xffffffffu, acc, 1);
        if (half == 0) g_rvpart[chunk][b][o] = acc;
    }
    gridbar();

    // ---------------- P8: output projection (8 tasks) ----
    for (int task = bid; task < 8; task += NB) {
        __syncthreads();
        int bb = tid >> 8, jj = tid & 255;
        int b = task * 2 + bb;
        smem.p8.rv[bb][jj] = g_rvpart[0][b][jj] + g_rvpart[1][b][jj];
        __syncthreads();
        int col = tid & 255;
        float acc = g_outhid[b][col] + b_rd[col];
#pragma unroll 8
        for (int j = 0; j < R * M; j++)
            acc = fmaf(smem.p8.rv[bb][j], W_rd[(size_t)j * O_OUT + col], acc);
        out[b * O_OUT + col] = acc;
    }
}

// ----------------- launch -----------------
extern "C" void kernel_launch(void* const* d_in, const int* in_sizes, int n_in,
                              void* d_out, int out_size) {
    (void)in_sizes; (void)n_in; (void)out_size;
    dnc_fused<<<NB, NT>>>(
        (const float*)d_in[0], (const float*)d_in[1], (const float*)d_in[2],
        (const float*)d_in[3], (const float*)d_in[4], (const float*)d_in[5],
        (const float*)d_in[6], (const float*)d_in[7], (const float*)d_in[8],
        (const float*)d_in[9], (const float*)d_in[10], (const float*)d_in[11],
        (const float*)d_in[12], (const float*)d_in[13], (const float*)d_in[14],
        (const float*)d_in[15], (const float*)d_in[16], (const float*)d_in[17],
        (const float*)d_in[18], (float*)d_out);
}

// round 3
// speedup vs baseline: 2.0580x; 2.0580x over previous
#include <cuda_runtime.h>
#include <math.h>

#define B 16
#define I_IN 256
#define H 512
#define O_OUT 256
#define A 1024
#define M 64
#define R 4
#define IFW 471
#define N4H 2048
#define NCOLS3 (IFW + O_OUT)   // 727

// interface offsets
#define OFF_KR     0
#define OFF_BETAR  256
#define OFF_KW     260
#define OFF_BETAW  324
#define OFF_ERASE  325
#define OFF_WRITEV 389
#define OFF_FREE   453
#define OFF_GA     457
#define OFF_GW     458
#define OFF_PI     459

// ----------------- device scratch -----------------
__device__ float  g_zpart[16][B][N4H];
__device__ float  g_h[B][H];
__device__ float  g_ifpart[4][B][NCOLS3];
__device__ float  g_iface[B][IFW];
__device__ float  g_outhid[B][O_OUT];
__device__ float  g_ww[B][A];
__device__ float  g_S[B][R];
__device__ float  g_T[B][R];
__device__ float  g_mem[B][A][M];
__device__ float  g_cr[B][R][A];
__device__ double g_PQ[B][R][A];        // packed (p,q)
__device__ double g_UVp[16][B][R][A];   // packed (u,v) partials, 2 per stripe

__device__ __forceinline__ float sigf(float x) { return 1.f / (1.f + __expf(-x)); }
__device__ __forceinline__ float oneplusf(float x) {
    return 1.f + (x > 20.f ? x : log1pf(__expf(x)));
}

// packed f32x2 helpers (double as bit-carrier)
__device__ __forceinline__ double pack2(float lo, float hi) {
    double d; asm("mov.b64 %0, {%1,%2};" : "=d"(d) : "f"(lo), "f"(hi)); return d;
}
__device__ __forceinline__ double splat2(float v) {
    double d; asm("mov.b64 %0, {%1,%1};" : "=d"(d) : "f"(v)); return d;
}
__device__ __forceinline__ void fma2(double& acc, double a, double b) {
    asm("fma.rn.f32x2 %0, %1, %2, %3;" : "=d"(acc) : "d"(a), "d"(b), "d"(acc));
}
__device__ __forceinline__ double add2(double a, double b) {
    double d; asm("add.rn.f32x2 %0, %1, %2;" : "=d"(d) : "d"(a), "d"(b)); return d;
}
__device__ __forceinline__ float2 unpack2(double d) {
    float2 f; asm("mov.b64 {%0,%1}, %2;" : "=f"(f.x), "=f"(f.y) : "d"(d)); return f;
}

// swizzle for pack table (idx = a*4 + r); flips bits [2:4] only, so idx..idx+3 stay contiguous
__device__ __forceinline__ int swz(int idx) { return idx ^ (((idx >> 9) & 7) << 2); }

template <int NT>
__device__ __forceinline__ float blockSum(float v, float* s_red) {
    int lane = threadIdx.x & 31, w = threadIdx.x >> 5;
#pragma unroll
    for (int o = 16; o; o >>= 1) v += __shfl_down_sync(0xffffffffu, v, o);
    if (lane == 0) s_red[w] = v;
    __syncthreads();
    if (w == 0) {
        float x = (lane < NT / 32) ? s_red[lane] : 0.f;
#pragma unroll
        for (int o = 16; o; o >>= 1) x += __shfl_down_sync(0xffffffffu, x, o);
        if (lane == 0) s_red[0] = x;
    }
    __syncthreads();
    float res = s_red[0];
    __syncthreads();
    return res;
}
template <int NT>
__device__ __forceinline__ float blockMax(float v, float* s_red) {
    int lane = threadIdx.x & 31, w = threadIdx.x >> 5;
#pragma unroll
    for (int o = 16; o; o >>= 1) v = fmaxf(v, __shfl_down_sync(0xffffffffu, v, o));
    if (lane == 0) s_red[w] = v;
    __syncthreads();
    if (w == 0) {
        float x = (lane < NT / 32) ? s_red[lane] : -1e30f;
#pragma unroll
        for (int o = 16; o; o >>= 1) x = fmaxf(x, __shfl_down_sync(0xffffffffu, x, o));
        if (lane == 0) s_red[0] = x;
    }
    __syncthreads();
    float res = s_red[0];
    __syncthreads();
    return res;
}

// ============ K1: z GEMM, k-split 16 chunks of 64, packed f32x2 ============
__global__ void __launch_bounds__(256, 1)
k1_zpart(const float* __restrict__ x, const float* __restrict__ h_prev,
         const float* __restrict__ rv_prev, const float* __restrict__ Wx,
         const float* __restrict__ Wh) {
    __shared__ double s_in2[B][64];   // pre-splatted inputs
    int tid = threadIdx.x;
    int ntile = blockIdx.x;           // 4 tiles of 512 cols
    int kc = blockIdx.y;              // 16 chunks of 64
    int kbase = kc * 64;
    for (int idx = tid; idx < B * 64; idx += 256) {
        int b = idx >> 6, kl = idx & 63;
        int kk = kbase + kl;
        float v;
        if (kk < 256) v = x[b * I_IN + kk];
        else if (kk < 512) v = rv_prev[b * 256 + (kk - 256)];
        else v = h_prev[b * H + (kk - 512)];
        s_in2[b][kl] = splat2(v);
    }
    __syncthreads();
    int n0 = ntile * 512 + tid * 2;
    const float* Wbase = (kbase < 512) ? (Wx + (size_t)kbase * N4H)
                                       : (Wh + (size_t)(kbase - 512) * N4H);
    const char* Wp = (const char*)(Wbase + n0);
    double acc2[B];
#pragma unroll
    for (int b = 0; b < B; b++) acc2[b] = 0.0;
#pragma unroll 4
    for (int kl = 0; kl < 64; kl++) {
        double w2 = *(const double*)(Wp + (size_t)kl * (N4H * 4));
#pragma unroll
        for (int b = 0; b < B; b++) fma2(acc2[b], s_in2[b][kl], w2);
    }
#pragma unroll
    for (int b = 0; b < B; b++)
        *(double*)&g_zpart[kc][b][n0] = acc2[b];
}

// ============ K2: reduce z partials + LSTM ============
__global__ void __launch_bounds__(512, 1)
k2_lstm(const float* __restrict__ c_prev, const float* __restrict__ b_lstm) {
    int idx = blockIdx.x * 512 + threadIdx.x;  // B*H = 8192
    int b = idx >> 9, hh = idx & 511;
    float zv[4];
#pragma unroll
    for (int g = 0; g < 4; g++) {
        int n = g * H + hh;
        float s = b_lstm[n];
#pragma unroll
        for (int kc = 0; kc < 16; kc++) s += g_zpart[kc][b][n];
        zv[g] = s;
    }
    float c = sigf(zv[1]) * c_prev[idx] + sigf(zv[0]) * tanhf(zv[2]);
    g_h[b][hh] = sigf(zv[3]) * tanhf(c);
}

// ============ K3: iface + out_hidden partial GEMM (k-split 4) ============
__global__ void __launch_bounds__(256, 1)
k3_ifpart(const float* __restrict__ W_if, const float* __restrict__ W_hid) {
    int idx = blockIdx.x * 256 + threadIdx.x;
    if (idx >= B * NCOLS3) return;
    int col = idx % NCOLS3, b = idx / NCOLS3;
    int kbase = blockIdx.y * 128;
    const float* hrow = g_h[b] + kbase;
    float acc = 0.f;
    if (col < IFW) {
        const float* W = W_if + (size_t)kbase * IFW + col;
#pragma unroll 16
        for (int k = 0; k < 128; k++) acc = fmaf(hrow[k], W[(size_t)k * IFW], acc);
    } else {
        int c2 = col - IFW;
        const float* W = W_hid + (size_t)kbase * O_OUT + c2;
#pragma unroll 16
        for (int k = 0; k < 128; k++) acc = fmaf(hrow[k], W[(size_t)k * O_OUT], acc);
    }
    g_ifpart[blockIdx.y][b][col] = acc;
}

// ============ K4: iface-sum + cwlog + usage/sort/alloc + ww + S,T (1 block/b) ====
__global__ void __launch_bounds__(512, 1)
k4_alloc(const float* __restrict__ rw_prev, const float* __restrict__ ww_prev,
         const float* __restrict__ usage_prev, const float* __restrict__ prec_prev,
         const float* __restrict__ mem_prev, const float* __restrict__ b_if,
         const float* __restrict__ b_hid) {
    int b = blockIdx.x;
    int tid = threadIdx.x;  // 512
    __shared__ float s_val[A];
    __shared__ float s_tmp[A];
    __shared__ int   s_idx[A];
    __shared__ float s_cw[A];
    __shared__ float s_red[16];
    __shared__ float s_scal[8];
    __shared__ float s_kw[M];

    // --- sum iface partials + bias (also out_hidden) ---
    for (int col = tid; col < NCOLS3; col += 512) {
        float s = g_ifpart[0][b][col] + g_ifpart[1][b][col] +
                  g_ifpart[2][b][col] + g_ifpart[3][b][col];
        if (col < IFW) g_iface[b][col] = s + b_if[col];
        else g_outhid[b][col - IFW] = s + b_hid[col - IFW];
    }
    __syncthreads();

    if (tid < M) s_kw[tid] = g_iface[b][OFF_KW + tid];
    if (tid == 0) {
        s_scal[0] = oneplusf(g_iface[b][OFF_BETAW]);
        s_scal[1] = sigf(g_iface[b][OFF_GA]);
        s_scal[2] = sigf(g_iface[b][OFF_GW]);
    }
    if (tid < R) s_scal[4 + tid] = sigf(g_iface[b][OFF_FREE + tid]);
    __syncthreads();

    float kn2 = 0.f;
#pragma unroll
    for (int m = 0; m < M; m++) { float v = s_kw[m]; kn2 = fmaf(v, v, kn2); }
    float knorm = sqrtf(kn2);
    float betaw = s_scal[0];
    // cwlog
    for (int ii = 0; ii < 2; ii++) {
        int a = tid + ii * 512;
        const float4* mrow = reinterpret_cast<const float4*>(mem_prev + ((size_t)(b * A + a)) * M);
        float d = 0.f, n = 0.f;
#pragma unroll
        for (int q = 0; q < 16; q++) {
            float4 v = mrow[q];
            int m0 = q * 4;
            d += v.x * s_kw[m0] + v.y * s_kw[m0 + 1] + v.z * s_kw[m0 + 2] + v.w * s_kw[m0 + 3];
            n += v.x * v.x + v.y * v.y + v.z * v.z + v.w * v.w;
        }
        s_cw[a] = betaw * d / (knorm * sqrtf(n) + 1e-6f);
    }
    // usage
    for (int ii = 0; ii < 2; ii++) {
        int a = tid + ii * 512;
        float psi = 1.f;
#pragma unroll
        for (int r = 0; r < R; r++)
            psi *= (1.f - s_scal[4 + r] * rw_prev[(b * R + r) * A + a]);
        float u = usage_prev[b * A + a], w = ww_prev[b * A + a];
        s_val[a] = (u + w - u * w) * psi;
        s_idx[a] = a;
    }
    __syncthreads();
    // bitonic sort ascending
    for (int k = 2; k <= A; k <<= 1) {
        for (int j = k >> 1; j > 0; j >>= 1) {
            for (int i = tid; i < A; i += 512) {
                int l = i ^ j;
                if (l > i) {
                    bool up = ((i & k) == 0);
                    float vi = s_val[i], vl = s_val[l];
                    if ((vi > vl) == up) {
                        s_val[i] = vl; s_val[l] = vi;
                        int t = s_idx[i]; s_idx[i] = s_idx[l]; s_idx[l] = t;
                    }
                }
            }
            __syncthreads();
        }
    }
    float su0 = s_val[tid], su1 = s_val[tid + 512];
    // inclusive cumprod
    {
        float* src = s_val;
        float* dst = s_tmp;
        for (int off = 1; off < A; off <<= 1) {
            for (int i = tid; i < A; i += 512)
                dst[i] = (i >= off) ? src[i - off] * src[i] : src[i];
            __syncthreads();
            float* t = src; src = dst; dst = t;
        }
    }
    {
        float cpe0 = (tid == 0) ? 1.f : s_val[tid - 1];
        float cpe1 = s_val[tid + 511];
        s_tmp[s_idx[tid]] = (1.f - su0) * cpe0;
        s_tmp[s_idx[tid + 512]] = (1.f - su1) * cpe1;
    }
    __syncthreads();
    // c_w softmax
    float l0 = s_cw[tid], l1 = s_cw[tid + 512];
    float mx = blockMax<512>(fmaxf(l0, l1), s_red);
    float e0 = __expf(l0 - mx), e1 = __expf(l1 - mx);
    float ssum = blockSum<512>(e0 + e1, s_red);
    float inv = 1.f / ssum;
    s_cw[tid] = e0 * inv;
    s_cw[tid + 512] = e1 * inv;
    __syncthreads();
    // ww + S,T
    float ga = s_scal[1], gw = s_scal[2];
    float sS[R] = {0, 0, 0, 0}, sT[R] = {0, 0, 0, 0};
    for (int ii = 0; ii < 2; ii++) {
        int a = tid + ii * 512;
        float wwv = gw * (ga * s_tmp[a] + (1.f - ga) * s_cw[a]);
        g_ww[b][a] = wwv;
        float pp = prec_prev[b * A + a];
#pragma unroll
        for (int r = 0; r < R; r++) {
            float rw = rw_prev[(b * R + r) * A + a];
            sS[r] = fmaf(pp, rw, sS[r]);
            sT[r] = fmaf(wwv, rw, sT[r]);
        }
    }
#pragma unroll
    for (int r = 0; r < R; r++) {
        float v = blockSum<512>(sS[r], s_red);
        if (tid == 0) g_S[b][r] = v;
        v = blockSum<512>(sT[r], s_red);
        if (tid == 0) g_T[b][r] = v;
    }
}

// ============ K57: mem write + c_r logits + link pass (block = (stripe, b)) ====
__global__ void __launch_bounds__(512, 1)
k57_mem_link(const float* __restrict__ mem_prev, const float* __restrict__ link_prev,
             const float* __restrict__ rw_prev) {
    __shared__ double s_pack[A * 4];          // 32 KB
    __shared__ float  s_kr[R][M];
    __shared__ float  s_er[M], s_wv[M];
    __shared__ float  s_beta[R], s_kn[R];
    int tid = threadIdx.x;                    // 512
    int stripe = blockIdx.x;                  // 8 stripes of 128 rows
    int b = blockIdx.y;
    int jbase = stripe * 128;

    // --- params ---
    if (tid < 256) {
        int r = tid >> 6, m = tid & 63;
        s_kr[r][m] = g_iface[b][OFF_KR + r * M + m];
    } else if (tid < 256 + M) {
        s_er[tid - 256] = sigf(g_iface[b][OFF_ERASE + (tid - 256)]);
    } else if (tid < 256 + 2 * M) {
        s_wv[tid - 256 - M] = g_iface[b][OFF_WRITEV + (tid - 256 - M)];
    }
    __syncthreads();
    if (tid < R) {
        s_beta[tid] = oneplusf(g_iface[b][OFF_BETAR + tid]);
        float s = 0.f;
#pragma unroll
        for (int m = 0; m < M; m++) { float v = s_kr[tid][m]; s = fmaf(v, v, s); }
        s_kn[tid] = sqrtf(s);
    }
    __syncthreads();

    // --- part 1: mem update + cr logits for rows [jbase, jbase+128) ---
    {
        int lane16 = tid & 15, m0 = lane16 * 4;
#pragma unroll
        for (int pass = 0; pass < 4; pass++) {
            int a = jbase + pass * 32 + (tid >> 4);
            float w = g_ww[b][a];
            float4 v = *reinterpret_cast<const float4*>(mem_prev + ((size_t)(b * A + a)) * M + m0);
            float n0 = v.x * (1.f - w * s_er[m0])     + w * s_wv[m0];
            float n1 = v.y * (1.f - w * s_er[m0 + 1]) + w * s_wv[m0 + 1];
            float n2 = v.z * (1.f - w * s_er[m0 + 2]) + w * s_wv[m0 + 2];
            float n3 = v.w * (1.f - w * s_er[m0 + 3]) + w * s_wv[m0 + 3];
            *reinterpret_cast<float4*>(&g_mem[b][a][m0]) = make_float4(n0, n1, n2, n3);
            float nn = n0 * n0 + n1 * n1 + n2 * n2 + n3 * n3;
            float d[R];
#pragma unroll
            for (int r = 0; r < R; r++)
                d[r] = n0 * s_kr[r][m0] + n1 * s_kr[r][m0 + 1] +
                       n2 * s_kr[r][m0 + 2] + n3 * s_kr[r][m0 + 3];
#pragma unroll
            for (int o = 8; o; o >>= 1) {
                nn += __shfl_xor_sync(0xffffffffu, nn, o);
#pragma unroll
                for (int r = 0; r < R; r++) d[r] += __shfl_xor_sync(0xffffffffu, d[r], o);
            }
            if (lane16 == 0) {
                float mn = sqrtf(nn);
#pragma unroll
                for (int r = 0; r < R; r++)
                    g_cr[b][r][a] = s_beta[r] * d[r] / (s_kn[r] * mn + 1e-6f);
            }
        }
    }

    // --- pack table ---
    for (int a = tid; a < A; a += 512) {
        float w = g_ww[b][a];
#pragma unroll
        for (int r = 0; r < R; r++) {
            float rw = rw_prev[(b * R + r) * A + a];
            s_pack[swz(a * 4 + r)] = pack2(rw, w * rw);
        }
    }
    __syncthreads();

    const float* Lp = link_prev + (size_t)b * A * A;

    // --- phase A: column partials (u,v); thread owns 4 cols, half the rows ---
    {
        int colbase = 4 * (tid & 255);
        int rhalf = tid >> 8;  // 0 or 1
        double uv[4][R];
#pragma unroll
        for (int c = 0; c < 4; c++)
#pragma unroll
            for (int r = 0; r < R; r++) uv[c][r] = 0.0;
#pragma unroll 4
        for (int i = 0; i < 64; i++) {
            int j = jbase + 2 * i + rhalf;
            float4 val = *reinterpret_cast<const float4*>(Lp + (size_t)j * A + colbase);
            int j4 = j * 4;
            double2 pk01 = *reinterpret_cast<const double2*>(&s_pack[swz(j4)]);
            double2 pk23 = *reinterpret_cast<const double2*>(&s_pack[swz(j4 + 2)]);
            double sx = splat2(val.x), sy = splat2(val.y);
            double sz = splat2(val.z), sw = splat2(val.w);
            fma2(uv[0][0], sx, pk01.x); fma2(uv[0][1], sx, pk01.y);
            fma2(uv[0][2], sx, pk23.x); fma2(uv[0][3], sx, pk23.y);
            fma2(uv[1][0], sy, pk01.x); fma2(uv[1][1], sy, pk01.y);
            fma2(uv[1][2], sy, pk23.x); fma2(uv[1][3], sy, pk23.y);
            fma2(uv[2][0], sz, pk01.x); fma2(uv[2][1], sz, pk01.y);
            fma2(uv[2][2], sz, pk23.x); fma2(uv[2][3], sz, pk23.y);
            fma2(uv[3][0], sw, pk01.x); fma2(uv[3][1], sw, pk01.y);
            fma2(uv[3][2], sw, pk23.x); fma2(uv[3][3], sw, pk23.y);
        }
        int sidx = 2 * stripe + rhalf;
#pragma unroll
        for (int c = 0; c < 4; c++)
#pragma unroll
            for (int r = 0; r < R; r++)
                g_UVp[sidx][b][r][colbase + c] = uv[c][r];
    }

    // --- phase B: row dots (p,q); 4 threads per row, 256 cols each (L2-hot) ---
    {
        int rowl = tid >> 2, quarter = tid & 3;
        int row = jbase + rowl;
        int cbase = quarter * 256;
        const float* Lr = Lp + (size_t)row * A + cbase;
        double pq[R] = {0.0, 0.0, 0.0, 0.0};
#pragma unroll 4
        for (int cs = 0; cs < 64; cs++) {
            float4 val = *reinterpret_cast<const float4*>(Lr + cs * 4);
            int col4 = (cbase + cs * 4) * 4;
            {
                double2 pk01 = *reinterpret_cast<const double2*>(&s_pack[swz(col4)]);
                double2 pk23 = *reinterpret_cast<const double2*>(&s_pack[swz(col4 + 2)]);
                double s = splat2(val.x);
                fma2(pq[0], s, pk01.x); fma2(pq[1], s, pk01.y);
                fma2(pq[2], s, pk23.x); fma2(pq[3], s, pk23.y);
            }
            {
                double2 pk01 = *reinterpret_cast<const double2*>(&s_pack[swz(col4 + 4)]);
                double2 pk23 = *reinterpret_cast<const double2*>(&s_pack[swz(col4 + 6)]);
                double s = splat2(val.y);
                fma2(pq[0], s, pk01.x); fma2(pq[1], s, pk01.y);
                fma2(pq[2], s, pk23.x); fma2(pq[3], s, pk23.y);
            }
            {
                double2 pk01 = *reinterpret_cast<const double2*>(&s_pack[swz(col4 + 8)]);
                double2 pk23 = *reinterpret_cast<const double2*>(&s_pack[swz(col4 + 10)]);
                double s = splat2(val.z);
                fma2(pq[0], s, pk01.x); fma2(pq[1], s, pk01.y);
                fma2(pq[2], s, pk23.x); fma2(pq[3], s, pk23.y);
            }
            {
                double2 pk01 = *reinterpret_cast<const double2*>(&s_pack[swz(col4 + 12)]);
                double2 pk23 = *reinterpret_cast<const double2*>(&s_pack[swz(col4 + 14)]);
                double s = splat2(val.w);
                fma2(pq[0], s, pk01.x); fma2(pq[1], s, pk01.y);
                fma2(pq[2], s, pk23.x); fma2(pq[3], s, pk23.y);
            }
        }
#pragma unroll
        for (int r = 0; r < R; r++) {
            pq[r] = add2(pq[r], __shfl_xor_sync(0xffffffffu, pq[r], 1));
            pq[r] = add2(pq[r], __shfl_xor_sync(0xffffffffu, pq[r], 2));
        }
        if (quarter == 0) {
#pragma unroll
            for (int r = 0; r < R; r++) g_PQ[b][r][row] = pq[r];
        }
    }
}

// ============ K8: cr softmax + read weights + rv GEMV + output (1 block/b) ====
__global__ void __launch_bounds__(512, 1)
k8_read_out(const float* __restrict__ rw_prev, const float* __restrict__ prec_prev,
            const float* __restrict__ W_rd, const float* __restrict__ b_rd,
            float* __restrict__ out) {
    int b = blockIdx.x;
    int tid = threadIdx.x;  // 512
    __shared__ float s_wr[R][A];        // 16 KB (first holds normalized cr, then wr)
    __shared__ float s_racc[16][R][M];  // 16 KB
    __shared__ float s_rv[R * M];
    __shared__ float s_out[2][O_OUT];
    __shared__ float s_pi[R][3];
    __shared__ float s_red[16];

    if (tid < R) {
        float l0 = g_iface[b][OFF_PI + tid * 3 + 0];
        float l1 = g_iface[b][OFF_PI + tid * 3 + 1];
        float l2 = g_iface[b][OFF_PI + tid * 3 + 2];
        float mx = fmaxf(l0, fmaxf(l1, l2));
        float e0 = __expf(l0 - mx), e1 = __expf(l1 - mx), e2 = __expf(l2 - mx);
        float inv = 1.f / (e0 + e1 + e2);
        s_pi[tid][0] = e0 * inv; s_pi[tid][1] = e1 * inv; s_pi[tid][2] = e2 * inv;
    }

    // --- softmax of c_r logits, into s_wr ---
#pragma unroll
    for (int r = 0; r < R; r++) {
        float l0 = g_cr[b][r][tid], l1 = g_cr[b][r][tid + 512];
        float mx = blockMax<512>(fmaxf(l0, l1), s_red);
        float e0 = __expf(l0 - mx), e1 = __expf(l1 - mx);
        float s = blockSum<512>(e0 + e1, s_red);
        float inv = 1.f / s;
        s_wr[r][tid] = e0 * inv;
        s_wr[r][tid + 512] = e1 * inv;
    }
    __syncthreads();

    // --- read weights ---
    for (int ii = 0; ii < 2; ii++) {
        int a = tid + ii * 512;
        float ww = g_ww[b][a];
        float pp = prec_prev[b * A + a];
#pragma unroll
        for (int r = 0; r < R; r++) {
            float rw = rw_prev[(b * R + r) * A + a];
            float2 PQ = unpack2(g_PQ[b][r][a]);
            double uvs = g_UVp[0][b][r][a];
#pragma unroll
            for (int s16 = 1; s16 < 16; s16++) uvs = add2(uvs, g_UVp[s16][b][r][a]);
            float2 UV = unpack2(uvs);
            float Sr = g_S[b][r], Tr = g_T[b][r];
            float fwd = (1.f - ww) * PQ.x - PQ.y + ww * (Sr - pp * rw);
            float bwd = (1.f - ww) * UV.x - UV.y + pp * (Tr - ww * rw);
            float cr = s_wr[r][a];
            s_wr[r][a] = s_pi[r][0] * bwd + s_pi[r][1] * cr + s_pi[r][2] * fwd;
        }
    }
    __syncthreads();

    // --- rv GEMV: warp w handles a = i*16 + w ---
    {
        int w = tid >> 5, lane = tid & 31;
        float acc[2][R] = {{0, 0, 0, 0}, {0, 0, 0, 0}};
#pragma unroll 4
        for (int i = 0; i < 64; i++) {
            int a = i * 16 + w;
            float m0 = g_mem[b][a][lane];
            float m1 = g_mem[b][a][lane + 32];
#pragma unroll
            for (int r = 0; r < R; r++) {
                float wr = s_wr[r][a];
                acc[0][r] = fmaf(wr, m0, acc[0][r]);
                acc[1][r] = fmaf(wr, m1, acc[1][r]);
            }
        }
#pragma unroll
        for (int r = 0; r < R; r++) {
            s_racc[w][r][lane] = acc[0][r];
            s_racc[w][r][lane + 32] = acc[1][r];
        }
    }
    __syncthreads();
    if (tid < R * M) {
        float s = 0.f;
#pragma unroll
        for (int w = 0; w < 16; w++) s += s_racc[w][tid >> 6][tid & 63];
        s_rv[tid] = s;
    }
    __syncthreads();

    // --- output projection ---
    {
        int half = tid >> 8, col = tid & 255;
        float acc = 0.f;
        const float* W = W_rd + (size_t)half * 128 * O_OUT + col;
#pragma unroll 8
        for (int j = 0; j < 128; j++)
            acc = fmaf(s_rv[half * 128 + j], W[(size_t)j * O_OUT], acc);
        s_out[half][col] = acc;
    }
    __syncthreads();
    if (tid < O_OUT) {
        out[b * O_OUT + tid] = s_out[0][tid] + s_out[1][tid] + g_outhid[b][tid] + b_rd[tid];
    }
}

// ----------------- launch -----------------
extern "C" void kernel_launch(void* const* d_in, const int* in_sizes, int n_in,
                              void* d_out, int out_size) {
    (void)in_sizes; (void)n_in; (void)out_size;
    const float* x          = (const float*)d_in[0];
    const float* h_prev     = (const float*)d_in[1];
    const float* c_prev     = (const float*)d_in[2];
    const float* mem_prev   = (const float*)d_in[3];
    const float* rw_prev    = (const float*)d_in[4];
    const float* ww_prev    = (const float*)d_in[5];
    const float* usage_prev = (const float*)d_in[6];
    const float* prec_prev  = (const float*)d_in[7];
    const float* link_prev  = (const float*)d_in[8];
    const float* rv_prev    = (const float*)d_in[9];
    const float* Wx         = (const float*)d_in[10];
    const float* Wh         = (const float*)d_in[11];
    const float* b_lstm     = (const float*)d_in[12];
    const float* W_hid      = (const float*)d_in[13];
    const float* b_hid      = (const float*)d_in[14];
    const float* W_if       = (const float*)d_in[15];
    const float* b_if       = (const float*)d_in[16];
    const float* W_rd       = (const float*)d_in[17];
    const float* b_rd       = (const float*)d_in[18];
    float* out = (float*)d_out;

    k1_zpart<<<dim3(4, 16), 256>>>(x, h_prev, rv_prev, Wx, Wh);
    k2_lstm<<<16, 512>>>(c_prev, b_lstm);
    k3_ifpart<<<dim3(46, 4), 256>>>(W_if, W_hid);
    k4_alloc<<<B, 512>>>(rw_prev, ww_prev, usage_prev, prec_prev, mem_prev, b_if, b_hid);
    k57_mem_link<<<dim3(8, B), 512>>>(mem_prev, link_prev, rw_prev);
    k8_read_out<<<B, 512>>>(rw_prev, prec_prev, W_rd, b_rd, out);
}